// round 16
// baseline (speedup 1.0000x reference)
#include <cuda_runtime.h>
#include <cuda_bf16.h>

// Problem dimensions (fixed by the dataset)
#define B_ 256
#define T_ 50
#define I_ 1024
#define H_ 2048
#define O_ 20

// ---------------------------------------------------------------------------
// Static device scratch (no allocation allowed anywhere)
// ---------------------------------------------------------------------------
__device__ __align__(16) float g_Hin[(size_t)B_ * T_ * H_];   // 104.9 MB: X @ W_ih^T, row m = b*T + t
__device__ __align__(16) float g_S[2][(size_t)B_ * H_];       // hidden spikes, double-buffered
__device__ __align__(16) float g_hmem[(size_t)B_ * H_];       // hidden membrane
__device__ float g_omem[B_ * O_];
__device__ float g_ospk[B_ * O_];
__device__ float g_osum[B_ * O_];
__device__ float g_mot [B_ * O_];
__device__ float g_alpha_h[H_];
__device__ float g_alpha_o[O_];

// ---------------------------------------------------------------------------
// Packed fp32x2 FMA (Blackwell FFMA2): exact paired fp32, 2x FFMA issue rate.
// Only reachable via PTX fma.rn.f32x2 (ptxas never auto-fuses it).
// ---------------------------------------------------------------------------
__device__ __forceinline__ float2 ffma2(float2 a, float2 b, float2 c) {
    unsigned long long ua = *reinterpret_cast<unsigned long long*>(&a);
    unsigned long long ub = *reinterpret_cast<unsigned long long*>(&b);
    unsigned long long uc = *reinterpret_cast<unsigned long long*>(&c);
    unsigned long long ud;
    asm("fma.rn.f32x2 %0, %1, %2, %3;" : "=l"(ud) : "l"(ua), "l"(ub), "l"(uc));
    return *reinterpret_cast<float2*>(&ud);
}

// ---------------------------------------------------------------------------
// Per-launch state init (runs every replay: launch must be deterministic)
// ---------------------------------------------------------------------------
__global__ void k_init(const float* __restrict__ tau_h, const float* __restrict__ tau_o) {
    int i = blockIdx.x * blockDim.x + threadIdx.x;
    if (i < B_ * H_) { g_hmem[i] = 0.f; g_S[0][i] = 0.f; }
    if (i < B_ * O_) { g_omem[i] = 0.f; g_ospk[i] = 0.f; g_osum[i] = 0.f; g_mot[i] = 0.f; }
    if (i < H_) g_alpha_h[i] = expf(-1.0f / tau_h[i]);
    if (i < O_) g_alpha_o[i] = expf(-1.0f / tau_o[i]);
}

// ---------------------------------------------------------------------------
// SGEMM: C[M,N] = A[M,K] @ W[N,K]^T  (fp32, f32x2 inner product, double-buffer
// global->reg->smem pipeline).
//   FUSE=false: A = Ain (binary input viewed [B*T, I]); C -> g_Hin
//   FUSE=true : A = g_S[t&1]; epilogue fuses membrane update + spike threshold,
//               writes g_hmem and g_S[(t+1)&1].
// Requires M%BM==0, N%BN==0, K%BK==0 (true for all our shapes).
// ---------------------------------------------------------------------------
template <int BM, int BN, int BK, int TM, int TN, bool FUSE>
__global__ void __launch_bounds__((BM / TM) * (BN / TN))
k_gemm(const float* __restrict__ Ain, const float* __restrict__ W,
       int M, int N, int K, int t) {
    constexpr int NT    = (BM / TM) * (BN / TN);
    constexpr int K4    = BK / 4;
    constexpr int nA4   = BM * K4 / NT;
    constexpr int nB4   = BN * K4 / NT;
    constexpr int TCOLS = BN / TN;
    static_assert(BM * K4 % NT == 0 && BN * K4 % NT == 0, "loader tiling");
    static_assert(TM % 4 == 0 && TN % 4 == 0, "thread tile multiple of 4");

    const float* A = FUSE ? &g_S[t & 1][0] : Ain;

    __shared__ __align__(16) float As[BK][BM];
    __shared__ __align__(16) float Bs[BK][BN];

    const int tid     = threadIdx.x;
    const int rowBase = blockIdx.y * BM;
    const int colBase = blockIdx.x * BN;
    const int trow    = tid / TCOLS;
    const int tcol    = tid % TCOLS;

    float2 acc[TM / 2][TN];
#pragma unroll
    for (int i = 0; i < TM / 2; i++)
#pragma unroll
        for (int j = 0; j < TN; j++) acc[i][j] = make_float2(0.f, 0.f);

    float4 pa[nA4], pb[nB4];

    // prefetch k-tile 0 into registers
#pragma unroll
    for (int s = 0; s < nA4; s++) {
        int idx = tid + s * NT;
        int r = idx / K4, kc = (idx % K4) * 4;
        pa[s] = *reinterpret_cast<const float4*>(&A[(size_t)(rowBase + r) * K + kc]);
    }
#pragma unroll
    for (int s = 0; s < nB4; s++) {
        int idx = tid + s * NT;
        int r = idx / K4, kc = (idx % K4) * 4;
        pb[s] = *reinterpret_cast<const float4*>(&W[(size_t)(colBase + r) * K + kc]);
    }

    const int ktiles = K / BK;
    for (int kt = 0; kt < ktiles; ++kt) {
        // registers -> smem (transposed: As[k][m], Bs[k][n])
#pragma unroll
        for (int s = 0; s < nA4; s++) {
            int idx = tid + s * NT;
            int r = idx / K4, kc = (idx % K4) * 4;
            As[kc + 0][r] = pa[s].x; As[kc + 1][r] = pa[s].y;
            As[kc + 2][r] = pa[s].z; As[kc + 3][r] = pa[s].w;
        }
#pragma unroll
        for (int s = 0; s < nB4; s++) {
            int idx = tid + s * NT;
            int r = idx / K4, kc = (idx % K4) * 4;
            Bs[kc + 0][r] = pb[s].x; Bs[kc + 1][r] = pb[s].y;
            Bs[kc + 2][r] = pb[s].z; Bs[kc + 3][r] = pb[s].w;
        }
        __syncthreads();

        // prefetch next k-tile (overlaps with compute)
        if (kt + 1 < ktiles) {
            const int k0 = (kt + 1) * BK;
#pragma unroll
            for (int s = 0; s < nA4; s++) {
                int idx = tid + s * NT;
                int r = idx / K4, kc = (idx % K4) * 4;
                pa[s] = *reinterpret_cast<const float4*>(&A[(size_t)(rowBase + r) * K + k0 + kc]);
            }
#pragma unroll
            for (int s = 0; s < nB4; s++) {
                int idx = tid + s * NT;
                int r = idx / K4, kc = (idx % K4) * 4;
                pb[s] = *reinterpret_cast<const float4*>(&W[(size_t)(colBase + r) * K + k0 + kc]);
            }
        }

        // inner product over this k-tile
#pragma unroll
        for (int kk = 0; kk < BK; ++kk) {
            float2 a2[TM / 2];
#pragma unroll
            for (int i = 0; i < TM / 4; i++) {
                float4 a4 = *reinterpret_cast<const float4*>(&As[kk][trow * TM + 4 * i]);
                a2[2 * i + 0] = make_float2(a4.x, a4.y);
                a2[2 * i + 1] = make_float2(a4.z, a4.w);
            }
            float bl[TN];
#pragma unroll
            for (int j = 0; j < TN; j += 4) {
                float4 b4 = *reinterpret_cast<const float4*>(&Bs[kk][tcol * TN + j]);
                bl[j] = b4.x; bl[j + 1] = b4.y; bl[j + 2] = b4.z; bl[j + 3] = b4.w;
            }
#pragma unroll
            for (int j = 0; j < TN; j++) {
                float2 b2 = make_float2(bl[j], bl[j]);
#pragma unroll
                for (int i = 0; i < TM / 2; i++)
                    acc[i][j] = ffma2(a2[i], b2, acc[i][j]);
            }
        }
        __syncthreads();
    }

    if (!FUSE) {
        // write C -> g_Hin, coalesced float4 stores
#pragma unroll
        for (int i = 0; i < TM; i++) {
            int row = rowBase + trow * TM + i;
            float* Crow = &g_Hin[(size_t)row * N + colBase + tcol * TN];
#pragma unroll
            for (int j = 0; j < TN; j += 4) {
                float4 v;
                v.x = (i & 1) ? acc[i / 2][j + 0].y : acc[i / 2][j + 0].x;
                v.y = (i & 1) ? acc[i / 2][j + 1].y : acc[i / 2][j + 1].x;
                v.z = (i & 1) ? acc[i / 2][j + 2].y : acc[i / 2][j + 2].x;
                v.w = (i & 1) ? acc[i / 2][j + 3].y : acc[i / 2][j + 3].x;
                *reinterpret_cast<float4*>(&Crow[j]) = v;
            }
        }
    } else {
        // fused hidden-membrane update + spike for step t
        const int cur = t & 1, nxt = (t + 1) & 1;
#pragma unroll
        for (int i = 0; i < TM; i++) {
            int b = rowBase + trow * TM + i;
#pragma unroll
            for (int j = 0; j < TN; j++) {
                int h = colBase + tcol * TN + j;
                size_t idx = (size_t)b * H_ + h;
                float a  = (i & 1) ? acc[i / 2][j].y : acc[i / 2][j].x;
                float hm = g_hmem[idx];
                float so = g_S[cur][idx];  // previous-step spike
                float v  = a + g_Hin[((size_t)b * T_ + t) * H_ + h]
                             + hm * g_alpha_h[h] * (1.0f - so);
                float sp = (v - 0.3f) > 0.0f ? 1.0f : 0.0f;
                g_hmem[idx]   = v;
                g_S[nxt][idx] = sp;
            }
        }
    }
}

// ---------------------------------------------------------------------------
// Output layer per timestep: o_mem update, output spike, o_sum, softmax-accum.
// One block per batch element, 128 threads; exploits binary spikes (skip zeros).
// ---------------------------------------------------------------------------
__global__ void k_out(const float* __restrict__ w_ho, int t) {
    const int b   = blockIdx.x;
    const int tid = threadIdx.x;  // 128
    const float* Srow = &g_S[(t + 1) & 1][(size_t)b * H_];

    float acc[O_];
#pragma unroll
    for (int o = 0; o < O_; o++) acc[o] = 0.f;

    for (int h = tid; h < H_; h += 128) {
        if (Srow[h] != 0.0f) {
#pragma unroll
            for (int o = 0; o < O_; o++) acc[o] += w_ho[(size_t)o * H_ + h];
        }
    }

    __shared__ float red[O_][128];
#pragma unroll
    for (int o = 0; o < O_; o++) red[o][tid] = acc[o];
    __syncthreads();

    __shared__ float smO[O_];
    float om = 0.f;
    if (tid < O_) {
        float s = 0.f;
        for (int i = 0; i < 128; i++) s += red[tid][i];
        const int idx = b * O_ + tid;
        om = g_omem[idx] * g_alpha_o[tid] * (1.0f - g_ospk[idx]) + s;
        float osp = (om - 0.3f) > 0.0f ? 1.0f : 0.0f;
        g_omem[idx] = om;
        g_ospk[idx] = osp;
        g_osum[idx] += osp;
        smO[tid] = om;
    }
    __syncthreads();
    if (tid < O_) {
        float mx = smO[0];
#pragma unroll
        for (int k = 1; k < O_; k++) mx = fmaxf(mx, smO[k]);
        float den = 0.f;
#pragma unroll
        for (int k = 0; k < O_; k++) den += expf(smO[k] - mx);
        g_mot[b * O_ + tid] += expf(om - mx) / den;
    }
}

// ---------------------------------------------------------------------------
// Final: out = [ o_sum / T ; mot ]  (tuple flattened in reference order)
// ---------------------------------------------------------------------------
__global__ void k_final(float* __restrict__ out) {
    int i = blockIdx.x * blockDim.x + threadIdx.x;
    if (i < B_ * O_) {
        out[i]           = g_osum[i] * (1.0f / (float)T_);
        out[B_ * O_ + i] = g_mot[i];
    }
}

// ---------------------------------------------------------------------------
// Launch: graph-capturable, allocation-free, deterministic
// ---------------------------------------------------------------------------
extern "C" void kernel_launch(void* const* d_in, const int* in_sizes, int n_in,
                              void* d_out, int out_size) {
    const float* inp   = (const float*)d_in[0];  // [B,T,I] binary fp32
    const float* w_ih  = (const float*)d_in[1];  // [H,I]
    const float* w_hh  = (const float*)d_in[2];  // [H,H]
    const float* w_ho  = (const float*)d_in[3];  // [O,H]
    const float* tau_h = (const float*)d_in[4];  // [H]
    const float* tau_o = (const float*)d_in[5];  // [O]
    float* out = (float*)d_out;

    // 1) state + decay-constant init (every launch)
    k_init<<<(B_ * H_ + 255) / 256, 256>>>(tau_h, tau_o);

    // 2) precompute input projection: g_Hin[B*T, H] = X[B*T, I] @ w_ih[H, I]^T
    {
        constexpr int BM = 64, BN = 64, BK = 16, TM = 4, TN = 4;
        dim3 grid(H_ / BN, (B_ * T_) / BM);
        k_gemm<BM, BN, BK, TM, TN, false><<<grid, (BM / TM) * (BN / TN)>>>(
            inp, w_ih, B_ * T_, H_, I_, 0);
    }

    // 3) timestep loop: fused recurrent GEMM + membrane/spike, then output layer
    for (int t = 0; t < T_; ++t) {
        constexpr int BM = 64, BN = 64, BK = 16, TM = 4, TN = 4;
        dim3 grid(H_ / BN, B_ / BM);
        k_gemm<BM, BN, BK, TM, TN, true><<<grid, (BM / TM) * (BN / TN)>>>(
            nullptr, w_hh, B_, H_, H_, t);
        k_out<<<B_, 128>>>(w_ho, t);
    }

    // 4) write outputs
    k_final<<<(B_ * O_ + 255) / 256, 256>>>(out);
}